// round 15
// baseline (speedup 1.0000x reference)
#include <cuda_runtime.h>
#include <cuda_bf16.h>
#include <math.h>

// Problem constants
#define NN 64
#define CC 256
#define SS 64
#define PP 16
#define KK 4
#define NB (NN*PP)   // 1024 attention batches
#define NR (NB*SS)   // 65536 rows

// Scratch (no cudaMalloc allowed)
__device__ float g_xt[NR*CC];           // (n,p,s,c) fp32
__device__ float g_xattn[NR*CC];        // attention out + residual
__device__ float g_protn[PP*KK*CC];
__device__ float g_clustered[PP*NN*KK*CC];
__device__ unsigned char g_idx[PP*NN*SS];
// tf32 planes (u32 bit patterns)
__device__ unsigned g_xq[NR*CC];        // X tf32
__device__ unsigned g_q [NR*CC];        // Q tf32
__device__ unsigned g_k [NR*CC];        // K tf32
__device__ unsigned g_vq[NR*CC];        // V tf32
__device__ unsigned g_h [NR*CC];        // head-concat out tf32
// tf32 weights [ws][k][n], ws = q,k,v,o
__device__ unsigned g_wt[4*256*256];

// ---------------------------------------------------------------------------
// helpers
// ---------------------------------------------------------------------------
__device__ __forceinline__ unsigned f2tf(float f) {
    unsigned u;
    asm("cvt.rna.tf32.f32 %0, %1;" : "=r"(u) : "f"(f));
    return u;
}

__device__ __forceinline__ void mma_tf32(float c[4], const unsigned a[4],
                                         unsigned b0, unsigned b1) {
    asm volatile(
        "mma.sync.aligned.m16n8k8.row.col.f32.tf32.tf32.f32 "
        "{%0,%1,%2,%3},{%4,%5,%6,%7},{%8,%9},{%0,%1,%2,%3};"
        : "+f"(c[0]), "+f"(c[1]), "+f"(c[2]), "+f"(c[3])
        : "r"(a[0]), "r"(a[1]), "r"(a[2]), "r"(a[3]), "r"(b0), "r"(b1));
}

// ---------------------------------------------------------------------------
// Kernel P1: weights -> tf32
// ---------------------------------------------------------------------------
__global__ void packw_kernel(const float* __restrict__ Wq, const float* __restrict__ Wk,
                             const float* __restrict__ Wv, const float* __restrict__ Wo) {
    int ws = blockIdx.y;
    int i = blockIdx.x*256 + threadIdx.x;
    const float* W = (ws == 0) ? Wq : (ws == 1) ? Wk : (ws == 2) ? Wv : Wo;
    g_wt[ws*65536 + i] = f2tf(W[i]);
}

// ---------------------------------------------------------------------------
// Kernel 0: transpose x (n,c,s,p) -> g_xt (n,p,s,c) + tf32 pack fused
// ---------------------------------------------------------------------------
__global__ void transpose_kernel(const float* __restrict__ x) {
    __shared__ float tile[256*17];
    int bx = blockIdx.x;
    int n = bx >> 6, s = bx & 63;
    int t = threadIdx.x;
    const float* src = x + (size_t)n*262144 + (size_t)s*16;
    #pragma unroll
    for (int w = 0; w < 16; w++) {
        int i = t + w*256;
        int c = i >> 4, pp = i & 15;
        tile[c*17 + pp] = src[(size_t)c*1024 + pp];
    }
    __syncthreads();
    float* dst = g_xt + (size_t)n*262144 + (size_t)s*256;
    unsigned* dq = g_xq + (size_t)n*262144 + (size_t)s*256;
    #pragma unroll
    for (int w = 0; w < 16; w++) {
        float v = tile[t*17 + w];
        dst[(size_t)w*16384 + t] = v;
        dq[(size_t)w*16384 + t] = f2tf(v);
    }
}

// ---------------------------------------------------------------------------
// qkv: [65536 x 256] x [256 x 768] tf32; 1024 CTAs x 128 thr, 2 CTAs/SM
// X tile 64 rows (stride 260), W tile 32 cols (stride 40). Warp = M1xN4 (16x32).
// smem: 64*260*4 + 256*40*4 = 107520 B
// ---------------------------------------------------------------------------
#define Q2_WS (64*260)                 // u32 offset of W tile
#define Q2_U32 (64*260 + 256*40)       // 26880 u32 = 107520 B

__global__ __launch_bounds__(128, 2) void qkv_kernel(
    const float* __restrict__ bq, const float* __restrict__ bk,
    const float* __restrict__ bv) {
    extern __shared__ unsigned sm[];
    unsigned* Xs = sm;
    unsigned* Ws = sm + Q2_WS;
    int t = threadIdx.x;
    int w = t >> 5, lane = t & 31;
    int g = lane >> 2, tg = lane & 3;
    int row0 = blockIdx.x * 64;

    {
        const uint4* xs = (const uint4*)(g_xq + (size_t)row0*256);
        for (int idx = t; idx < 4096; idx += 128) {
            int r = idx >> 6, c4 = idx & 63;
            *(uint4*)(Xs + r*260 + 4*c4) = xs[idx];
        }
    }

    int rowA = w*16 + g;   // warp w: rows w*16 .. w*16+15

    for (int nt = 0; nt < 24; nt++) {
        int sel = nt >> 3, nto = nt & 7;
        __syncthreads();
        {
            const unsigned* wsrc = g_wt + sel*65536 + nto*32;
            for (int idx = t; idx < 2048; idx += 128) {
                int k = idx >> 3, c4 = idx & 7;
                *(uint4*)(Ws + k*40 + 4*c4) = *(const uint4*)(wsrc + k*256 + 4*c4);
            }
        }
        __syncthreads();

        float acc[4][4];
        #pragma unroll
        for (int nf = 0; nf < 4; nf++)
            #pragma unroll
            for (int j = 0; j < 4; j++) acc[nf][j] = 0.f;

        unsigned aP[2][4], bP[2][4][2];
        {
            int ab = rowA*260 + tg;
            aP[0][0] = Xs[ab];     aP[0][1] = Xs[ab + 8*260];
            aP[0][2] = Xs[ab + 4]; aP[0][3] = Xs[ab + 8*260 + 4];
            int w0 = tg*40, w1 = (tg + 4)*40;
            #pragma unroll
            for (int nf = 0; nf < 4; nf++) {
                int col = nf*8 + g;
                bP[0][nf][0] = Ws[w0 + col]; bP[0][nf][1] = Ws[w1 + col];
            }
        }
        #pragma unroll
        for (int s = 0; s < 32; s++) {
            int c = s & 1, nx = c ^ 1;
            if (s < 31) {
                int ab = rowA*260 + 8*(s+1) + tg;
                aP[nx][0] = Xs[ab];     aP[nx][1] = Xs[ab + 8*260];
                aP[nx][2] = Xs[ab + 4]; aP[nx][3] = Xs[ab + 8*260 + 4];
                int w0 = (8*(s+1) + tg)*40, w1 = (8*(s+1) + tg + 4)*40;
                #pragma unroll
                for (int nf = 0; nf < 4; nf++) {
                    int col = nf*8 + g;
                    bP[nx][nf][0] = Ws[w0 + col]; bP[nx][nf][1] = Ws[w1 + col];
                }
            }
            #pragma unroll
            for (int nf = 0; nf < 4; nf++)
                mma_tf32(acc[nf], aP[c], bP[c][nf][0], bP[c][nf][1]);
        }

        const float* bias = (sel == 0) ? bq : (sel == 1) ? bk : bv;
        unsigned* dst = (sel == 0) ? g_q : (sel == 1) ? g_k : g_vq;
        size_t rg0 = (size_t)(row0 + rowA), rg1 = rg0 + 8;
        #pragma unroll
        for (int nf = 0; nf < 4; nf++) {
            int mcol = nto*32 + nf*8 + 2*tg;
            float b0 = bias[mcol], b1 = bias[mcol + 1];
            uint2 o0, o1;
            o0.x = f2tf(acc[nf][0] + b0); o0.y = f2tf(acc[nf][1] + b1);
            o1.x = f2tf(acc[nf][2] + b0); o1.y = f2tf(acc[nf][3] + b1);
            *(uint2*)(dst + rg0*256 + mcol) = o0;
            *(uint2*)(dst + rg1*256 + mcol) = o1;
        }
    }
}

// ---------------------------------------------------------------------------
// core: per (batch, head): scores + warp-local softmax + S@V. 128 thr, 4 CTAs/SM
// ---------------------------------------------------------------------------
#define C_Q 0
#define C_K (64*68)
#define C_V (2*64*68)
#define C_U32 (3*64*68)    // 52224 B

__global__ __launch_bounds__(128, 4) void core_kernel() {
    extern __shared__ unsigned sm[];
    int t = threadIdx.x;
    int w = t >> 5, lane = t & 31;
    int g = lane >> 2, tg = lane & 3;
    int b = blockIdx.x, h = blockIdx.y;
    size_t rbase = (size_t)b * 64;

    for (int idx = t; idx < 1024; idx += 128) {
        int s = idx >> 4, c4 = idx & 15;
        *(uint4*)(sm + C_Q + s*68 + 4*c4) = *(const uint4*)(g_q + (rbase + s)*256 + h*64 + 4*c4);
        *(uint4*)(sm + C_K + s*68 + 4*c4) = *(const uint4*)(g_k + (rbase + s)*256 + h*64 + 4*c4);
    }
    for (int idx = t; idx < 4096; idx += 128) {
        int s = idx >> 6, d = idx & 63;
        sm[C_V + d*68 + s] = g_vq[(rbase + s)*256 + h*64 + d];
    }
    __syncthreads();

    int rowA = w*16 + g;

    float sc[8][4];
    #pragma unroll
    for (int i = 0; i < 8; i++) { sc[i][0] = sc[i][1] = sc[i][2] = sc[i][3] = 0.f; }
    #pragma unroll
    for (int s8 = 0; s8 < 8; s8++) {
        unsigned a[4];
        int ab = C_Q + rowA*68 + 8*s8 + tg;
        a[0] = sm[ab]; a[1] = sm[ab + 8*68]; a[2] = sm[ab + 4]; a[3] = sm[ab + 8*68 + 4];
        #pragma unroll
        for (int nf = 0; nf < 8; nf++) {
            int bb = C_K + (nf*8 + g)*68 + 8*s8 + tg;
            mma_tf32(sc[nf], a, sm[bb], sm[bb + 4]);
        }
    }

    const float NI = -3.402823466e38f;
    int rA = rowA, rB = rowA + 8;
    float mA = NI, mB = NI;
    #pragma unroll
    for (int nf = 0; nf < 8; nf++) {
        int c0 = nf*8 + 2*tg, c1 = c0 + 1;
        sc[nf][0] = (c0 <= rA) ? sc[nf][0]*0.125f : NI;
        sc[nf][1] = (c1 <= rA) ? sc[nf][1]*0.125f : NI;
        sc[nf][2] = (c0 <= rB) ? sc[nf][2]*0.125f : NI;
        sc[nf][3] = (c1 <= rB) ? sc[nf][3]*0.125f : NI;
        mA = fmaxf(mA, fmaxf(sc[nf][0], sc[nf][1]));
        mB = fmaxf(mB, fmaxf(sc[nf][2], sc[nf][3]));
    }
    mA = fmaxf(mA, __shfl_xor_sync(0xffffffffu, mA, 1));
    mA = fmaxf(mA, __shfl_xor_sync(0xffffffffu, mA, 2));
    mB = fmaxf(mB, __shfl_xor_sync(0xffffffffu, mB, 1));
    mB = fmaxf(mB, __shfl_xor_sync(0xffffffffu, mB, 2));
    float sA = 0.f, sB = 0.f;
    #pragma unroll
    for (int nf = 0; nf < 8; nf++) {
        int c0 = nf*8 + 2*tg, c1 = c0 + 1;
        float e0 = (c0 <= rA) ? __expf(sc[nf][0] - mA) : 0.f;
        float e1 = (c1 <= rA) ? __expf(sc[nf][1] - mA) : 0.f;
        float e2 = (c0 <= rB) ? __expf(sc[nf][2] - mB) : 0.f;
        float e3 = (c1 <= rB) ? __expf(sc[nf][3] - mB) : 0.f;
        sA += e0 + e1; sB += e2 + e3;
        sc[nf][0] = e0; sc[nf][1] = e1; sc[nf][2] = e2; sc[nf][3] = e3;
    }
    sA += __shfl_xor_sync(0xffffffffu, sA, 1);
    sA += __shfl_xor_sync(0xffffffffu, sA, 2);
    sB += __shfl_xor_sync(0xffffffffu, sB, 1);
    sB += __shfl_xor_sync(0xffffffffu, sB, 2);
    float iA = 1.f / sA, iB = 1.f / sB;
    unsigned P[8][4];
    #pragma unroll
    for (int nf = 0; nf < 8; nf++) {
        P[nf][0] = f2tf(sc[nf][0] * iA);
        P[nf][1] = f2tf(sc[nf][1] * iA);
        P[nf][2] = f2tf(sc[nf][2] * iB);
        P[nf][3] = f2tf(sc[nf][3] * iB);
    }

    float ha[8][4];
    #pragma unroll
    for (int i = 0; i < 8; i++) { ha[i][0] = ha[i][1] = ha[i][2] = ha[i][3] = 0.f; }
    int srcLo = (lane & 28) | (tg >> 1);
    int srcHi = srcLo + 2;
    bool odd = (tg & 1);
    #pragma unroll
    for (int s8 = 0; s8 < 8; s8++) {
        unsigned q00 = __shfl_sync(0xffffffffu, P[s8][0], srcLo);
        unsigned q01 = __shfl_sync(0xffffffffu, P[s8][1], srcLo);
        unsigned q10 = __shfl_sync(0xffffffffu, P[s8][2], srcLo);
        unsigned q11 = __shfl_sync(0xffffffffu, P[s8][3], srcLo);
        unsigned r00 = __shfl_sync(0xffffffffu, P[s8][0], srcHi);
        unsigned r01 = __shfl_sync(0xffffffffu, P[s8][1], srcHi);
        unsigned r10 = __shfl_sync(0xffffffffu, P[s8][2], srcHi);
        unsigned r11 = __shfl_sync(0xffffffffu, P[s8][3], srcHi);
        unsigned a[4];
        a[0] = odd ? q01 : q00;
        a[1] = odd ? q11 : q10;
        a[2] = odd ? r01 : r00;
        a[3] = odd ? r11 : r10;
        #pragma unroll
        for (int nf = 0; nf < 8; nf++) {
            int bb = C_V + (nf*8 + g)*68 + 8*s8 + tg;
            mma_tf32(ha[nf], a, sm[bb], sm[bb + 4]);
        }
    }

    #pragma unroll
    for (int nf = 0; nf < 8; nf++) {
        int gcol = h*64 + nf*8 + 2*tg;
        uint2 o0, o1;
        o0.x = f2tf(ha[nf][0]); o0.y = f2tf(ha[nf][1]);
        o1.x = f2tf(ha[nf][2]); o1.y = f2tf(ha[nf][3]);
        *(uint2*)(g_h + (rbase + rowA)*256 + gcol) = o0;
        *(uint2*)(g_h + (rbase + rowA + 8)*256 + gcol) = o1;
    }
}

// ---------------------------------------------------------------------------
// kout: [65536 x 256] x Wo + bo + residual; 1024 CTAs x 128 thr, 2 CTAs/SM
// ---------------------------------------------------------------------------
__global__ __launch_bounds__(128, 2) void kout_kernel(const float* __restrict__ bo) {
    extern __shared__ unsigned sm[];
    unsigned* Xs = sm;
    unsigned* Ws = sm + Q2_WS;
    int t = threadIdx.x;
    int w = t >> 5, lane = t & 31;
    int g = lane >> 2, tg = lane & 3;
    int row0 = blockIdx.x * 64;

    {
        const uint4* xs = (const uint4*)(g_h + (size_t)row0*256);
        for (int idx = t; idx < 4096; idx += 128) {
            int r = idx >> 6, c4 = idx & 63;
            *(uint4*)(Xs + r*260 + 4*c4) = xs[idx];
        }
    }

    int rowA = w*16 + g;

    for (int nt = 0; nt < 8; nt++) {
        __syncthreads();
        {
            const unsigned* wsrc = g_wt + 3*65536 + nt*32;
            for (int idx = t; idx < 2048; idx += 128) {
                int k = idx >> 3, c4 = idx & 7;
                *(uint4*)(Ws + k*40 + 4*c4) = *(const uint4*)(wsrc + k*256 + 4*c4);
            }
        }
        __syncthreads();

        float acc[4][4];
        #pragma unroll
        for (int nf = 0; nf < 4; nf++)
            #pragma unroll
            for (int j = 0; j < 4; j++) acc[nf][j] = 0.f;

        unsigned aP[2][4], bP[2][4][2];
        {
            int ab = rowA*260 + tg;
            aP[0][0] = Xs[ab];     aP[0][1] = Xs[ab + 8*260];
            aP[0][2] = Xs[ab + 4]; aP[0][3] = Xs[ab + 8*260 + 4];
            int w0 = tg*40, w1 = (tg + 4)*40;
            #pragma unroll
            for (int nf = 0; nf < 4; nf++) {
                int col = nf*8 + g;
                bP[0][nf][0] = Ws[w0 + col]; bP[0][nf][1] = Ws[w1 + col];
            }
        }
        #pragma unroll
        for (int s = 0; s < 32; s++) {
            int c = s & 1, nx = c ^ 1;
            if (s < 31) {
                int ab = rowA*260 + 8*(s+1) + tg;
                aP[nx][0] = Xs[ab];     aP[nx][1] = Xs[ab + 8*260];
                aP[nx][2] = Xs[ab + 4]; aP[nx][3] = Xs[ab + 8*260 + 4];
                int w0 = (8*(s+1) + tg)*40, w1 = (8*(s+1) + tg + 4)*40;
                #pragma unroll
                for (int nf = 0; nf < 4; nf++) {
                    int col = nf*8 + g;
                    bP[nx][nf][0] = Ws[w0 + col]; bP[nx][nf][1] = Ws[w1 + col];
                }
            }
            #pragma unroll
            for (int nf = 0; nf < 4; nf++)
                mma_tf32(acc[nf], aP[c], bP[c][nf][0], bP[c][nf][1]);
        }

        size_t rg0 = (size_t)(row0 + rowA), rg1 = rg0 + 8;
        #pragma unroll
        for (int nf = 0; nf < 4; nf++) {
            int mcol = nt*32 + nf*8 + 2*tg;
            float b0 = bo[mcol], b1 = bo[mcol + 1];
            float2 x0 = *(const float2*)(g_xt + rg0*256 + mcol);
            float2 x1 = *(const float2*)(g_xt + rg1*256 + mcol);
            *(float2*)(g_xattn + rg0*256 + mcol) =
                make_float2(acc[nf][0] + b0 + x0.x, acc[nf][1] + b1 + x0.y);
            *(float2*)(g_xattn + rg1*256 + mcol) =
                make_float2(acc[nf][2] + b0 + x1.x, acc[nf][3] + b1 + x1.y);
        }
    }
}

// ---------------------------------------------------------------------------
// Kernel 1: normalize prototypes
// ---------------------------------------------------------------------------
__global__ void protonorm_kernel(const float* __restrict__ prot) {
    int r = blockIdx.x;
    int t = threadIdx.x;
    float v = prot[r*256 + t];
    float sq = v * v;
    #pragma unroll
    for (int off = 16; off > 0; off >>= 1)
        sq += __shfl_down_sync(0xffffffffu, sq, off);
    __shared__ float red[8];
    if ((t & 31) == 0) red[t >> 5] = sq;
    __syncthreads();
    __shared__ float rn;
    if (t == 0) {
        float sum = 0.f;
        #pragma unroll
        for (int i = 0; i < 8; i++) sum += red[i];
        rn = rsqrtf(sum);
    }
    __syncthreads();
    g_protn[r*256 + t] = v * rn;
}

// ---------------------------------------------------------------------------
// Kernel 2: instance-norm + dot + argmax -> hard idx
// ---------------------------------------------------------------------------
__global__ __launch_bounds__(256) void assign_kernel() {
    int p = blockIdx.x, n = blockIdx.y;
    extern __shared__ float smf[];
    float* Xs = smf;
    float* P  = Xs + 16384;
    float* MU = P + 1024;
    float* RS = MU + 256;
    int t = threadIdx.x;
    const float* src = g_xt + (size_t)(n*16 + p) * 16384;
    for (int i = t; i < 16384; i += 256) Xs[i] = src[i];
    const float* psrc = g_protn + p*1024;
    for (int i = t; i < 1024; i += 256) P[i] = psrc[i];
    __syncthreads();

    {
        float s1 = 0.f, s2 = 0.f;
        #pragma unroll
        for (int s = 0; s < 64; s++) {
            float v = Xs[s*256 + t];
            s1 += v; s2 += v*v;
        }
        float mu = s1 * 0.015625f;
        float var = s2 * 0.015625f - mu*mu;
        MU[t] = mu;
        RS[t] = rsqrtf(var + 1e-5f);
    }
    __syncthreads();

    int w = t >> 5, lane = t & 31;
    #pragma unroll
    for (int it = 0; it < 8; it++) {
        int s = w*8 + it;
        float d0 = 0.f, d1 = 0.f, d2 = 0.f, d3 = 0.f;
        #pragma unroll
        for (int cc = 0; cc < 8; cc++) {
            int c = lane + 32*cc;
            float y = (Xs[s*256 + c] - MU[c]) * RS[c];
            d0 = fmaf(y, P[c],       d0);
            d1 = fmaf(y, P[256 + c], d1);
            d2 = fmaf(y, P[512 + c], d2);
            d3 = fmaf(y, P[768 + c], d3);
        }
        #pragma unroll
        for (int off = 16; off > 0; off >>= 1) {
            d0 += __shfl_down_sync(0xffffffffu, d0, off);
            d1 += __shfl_down_sync(0xffffffffu, d1, off);
            d2 += __shfl_down_sync(0xffffffffu, d2, off);
            d3 += __shfl_down_sync(0xffffffffu, d3, off);
        }
        if (lane == 0) {
            int best = 0; float bv = d0;
            if (d1 > bv) { bv = d1; best = 1; }
            if (d2 > bv) { bv = d2; best = 2; }
            if (d3 > bv) { bv = d3; best = 3; }
            g_idx[(p*64 + n)*64 + s] = (unsigned char)best;
        }
    }
}

// ---------------------------------------------------------------------------
// Kernel 3: mode over parts -> cluster_indices (as float)
// ---------------------------------------------------------------------------
__global__ void mode_kernel(float* __restrict__ outci) {
    int id = blockIdx.x*256 + threadIdx.x;
    if (id >= NN*SS) return;
    int n = id >> 6, s = id & 63;
    int c0 = 0, c1 = 0, c2 = 0, c3 = 0;
    #pragma unroll
    for (int p = 0; p < 16; p++) {
        int a = g_idx[(p*64 + n)*64 + s];
        c0 += (a == 0); c1 += (a == 1); c2 += (a == 2); c3 += (a == 3);
    }
    int best = 0, bc = c0;
    if (c1 > bc) { bc = c1; best = 1; }
    if (c2 > bc) { bc = c2; best = 2; }
    if (c3 > bc) { bc = c3; best = 3; }
    outci[id] = (float)best;
}

// ---------------------------------------------------------------------------
// Kernel 5: scatter-max pooling
// ---------------------------------------------------------------------------
__global__ __launch_bounds__(256) void scatter_kernel() {
    int p = blockIdx.x, n = blockIdx.y, t = threadIdx.x;
    __shared__ unsigned char ids[64];
    if (t < 64) ids[t] = g_idx[(p*64 + n)*64 + t];
    __syncthreads();
    int c0 = 0, c1 = 0, c2 = 0, c3 = 0;
    #pragma unroll 8
    for (int s = 0; s < 64; s++) {
        int a = ids[s];
        c0 += (a == 0); c1 += (a == 1); c2 += (a == 2); c3 += (a == 3);
    }
    const float* src = g_xattn + (size_t)(n*16 + p)*16384 + t;
    float m0 = -3.402823466e38f, m1 = m0, m2 = m0, m3 = m0;
    #pragma unroll 8
    for (int s = 0; s < 64; s++) {
        float v = src[s*256];
        int a = ids[s];
        if (a == 0) m0 = fmaxf(m0, v);
        else if (a == 1) m1 = fmaxf(m1, v);
        else if (a == 2) m2 = fmaxf(m2, v);
        else m3 = fmaxf(m3, v);
    }
    if (c0 < 64) m0 = fmaxf(m0, 0.f);
    if (c1 < 64) m1 = fmaxf(m1, 0.f);
    if (c2 < 64) m2 = fmaxf(m2, 0.f);
    if (c3 < 64) m3 = fmaxf(m3, 0.f);
    float* dst = g_clustered + (size_t)(p*64 + n)*1024 + t;
    dst[0]   = m0;
    dst[256] = m1;
    dst[512] = m2;
    dst[768] = m3;
}

// ---------------------------------------------------------------------------
// Kernel 6: per-part FC
// ---------------------------------------------------------------------------
__global__ __launch_bounds__(256) void fc_kernel(const float* __restrict__ fcb,
                                                 float* __restrict__ out) {
    int p = blockIdx.x, n0 = blockIdx.y * 16, t = threadIdx.x;
    extern __shared__ float cl[];
    for (int nn = 0; nn < 16; nn++) {
        const float* src = g_clustered + (size_t)(p*64 + n0 + nn)*1024;
        for (int i = t; i < 1024; i += 256) cl[nn*1024 + i] = src[i];
    }
    __syncthreads();
    int o0 = t & 63, g = t >> 6;
    float acc[4][4];
    #pragma unroll
    for (int a = 0; a < 4; a++)
        #pragma unroll
        for (int bb = 0; bb < 4; bb++) acc[a][bb] = 0.f;
    const float* F = fcb + (size_t)p*1024*256 + o0;
    for (int kc = 0; kc < 1024; kc++) {
        float wv[4], cv[4];
        #pragma unroll
        for (int bb = 0; bb < 4; bb++) wv[bb] = F[(size_t)kc*256 + 64*bb];
        #pragma unroll
        for (int a = 0; a < 4; a++) cv[a] = cl[(g*4 + a)*1024 + kc];
        #pragma unroll
        for (int a = 0; a < 4; a++)
            #pragma unroll
            for (int bb = 0; bb < 4; bb++)
                acc[a][bb] = fmaf(cv[a], wv[bb], acc[a][bb]);
    }
    #pragma unroll
    for (int a = 0; a < 4; a++) {
        int n = n0 + g*4 + a;
        #pragma unroll
        for (int bb = 0; bb < 4; bb++) {
            int o = o0 + 64*bb;
            out[(size_t)n*4096 + o*16 + p] = acc[a][bb];
        }
    }
}

// ---------------------------------------------------------------------------
extern "C" void kernel_launch(void* const* d_in, const int* in_sizes, int n_in,
                              void* d_out, int out_size) {
    const float* x    = (const float*)d_in[0];
    const float* prot = (const float*)d_in[1];
    const float* Wq   = (const float*)d_in[2];
    const float* bq   = (const float*)d_in[3];
    const float* Wk   = (const float*)d_in[4];
    const float* bk   = (const float*)d_in[5];
    const float* Wv   = (const float*)d_in[6];
    const float* bv   = (const float*)d_in[7];
    const float* Wo   = (const float*)d_in[8];
    const float* bo   = (const float*)d_in[9];
    const float* fcb  = (const float*)d_in[10];
    float* out = (float*)d_out;

    cudaFuncSetAttribute(qkv_kernel,  cudaFuncAttributeMaxDynamicSharedMemorySize, Q2_U32*4);
    cudaFuncSetAttribute(kout_kernel, cudaFuncAttributeMaxDynamicSharedMemorySize, Q2_U32*4);
    cudaFuncSetAttribute(core_kernel, cudaFuncAttributeMaxDynamicSharedMemorySize, C_U32*4);
    cudaFuncSetAttribute(assign_kernel, cudaFuncAttributeMaxDynamicSharedMemorySize, 71680);
    cudaFuncSetAttribute(fc_kernel, cudaFuncAttributeMaxDynamicSharedMemorySize, 65536);

    transpose_kernel<<<NN*SS, 256>>>(x);
    packw_kernel<<<dim3(256, 4), 256>>>(Wq, Wk, Wv, Wo);
    qkv_kernel<<<1024, 128, Q2_U32*4>>>(bq, bk, bv);
    core_kernel<<<dim3(NB, 4), 128, C_U32*4>>>();
    kout_kernel<<<1024, 128, Q2_U32*4>>>(bo);
    protonorm_kernel<<<PP*KK, 256>>>(prot);
    assign_kernel<<<dim3(PP, NN), 256, 71680>>>();
    if (out_size >= NN*CC*PP + NN*SS)
        mode_kernel<<<16, 256>>>(out + NN*CC*PP);
    scatter_kernel<<<dim3(PP, NN), 256>>>();
    fc_kernel<<<dim3(PP, 4), 256, 65536>>>(fcb, out);
}

// round 17
// speedup vs baseline: 1.1863x; 1.1863x over previous
#include <cuda_runtime.h>
#include <cuda_bf16.h>
#include <math.h>

// Problem constants
#define NN 64
#define CC 256
#define SS 64
#define PP 16
#define KK 4
#define NB (NN*PP)   // 1024 attention batches
#define NR (NB*SS)   // 65536 rows

// Scratch (no cudaMalloc allowed)
__device__ float g_xt[NR*CC];           // (n,p,s,c) fp32
__device__ float g_protn[PP*KK*CC];
__device__ float g_clustered[PP*NN*KK*CC];
__device__ unsigned char g_idx[PP*NN*SS];
// tf32 planes (u32 bit patterns)
__device__ unsigned g_xq[NR*CC];        // X tf32
__device__ unsigned g_q [NR*CC];        // Q tf32
__device__ unsigned g_k [NR*CC];        // K tf32
__device__ unsigned g_vq[NR*CC];        // V tf32
__device__ unsigned g_h [NR*CC];        // head-concat out tf32
// tf32 weights [ws][k][n], ws = q,k,v,o
__device__ unsigned g_wt[4*256*256];

// ---------------------------------------------------------------------------
// helpers
// ---------------------------------------------------------------------------
__device__ __forceinline__ unsigned f2tf(float f) {
    unsigned u;
    asm("cvt.rna.tf32.f32 %0, %1;" : "=r"(u) : "f"(f));
    return u;
}

__device__ __forceinline__ void mma_tf32(float c[4], const unsigned a[4],
                                         unsigned b0, unsigned b1) {
    asm volatile(
        "mma.sync.aligned.m16n8k8.row.col.f32.tf32.tf32.f32 "
        "{%0,%1,%2,%3},{%4,%5,%6,%7},{%8,%9},{%0,%1,%2,%3};"
        : "+f"(c[0]), "+f"(c[1]), "+f"(c[2]), "+f"(c[3])
        : "r"(a[0]), "r"(a[1]), "r"(a[2]), "r"(a[3]), "r"(b0), "r"(b1));
}

// ---------------------------------------------------------------------------
// Kernel P1: weights -> tf32
// ---------------------------------------------------------------------------
__global__ void packw_kernel(const float* __restrict__ Wq, const float* __restrict__ Wk,
                             const float* __restrict__ Wv, const float* __restrict__ Wo) {
    int ws = blockIdx.y;
    int i = blockIdx.x*256 + threadIdx.x;
    const float* W = (ws == 0) ? Wq : (ws == 1) ? Wk : (ws == 2) ? Wv : Wo;
    g_wt[ws*65536 + i] = f2tf(W[i]);
}

// ---------------------------------------------------------------------------
// Kernel 0: transpose x (n,c,s,p) -> g_xt (n,p,s,c) + tf32 pack fused
// ---------------------------------------------------------------------------
__global__ void transpose_kernel(const float* __restrict__ x) {
    __shared__ float tile[256*17];
    int bx = blockIdx.x;
    int n = bx >> 6, s = bx & 63;
    int t = threadIdx.x;
    const float* src = x + (size_t)n*262144 + (size_t)s*16;
    #pragma unroll
    for (int w = 0; w < 16; w++) {
        int i = t + w*256;
        int c = i >> 4, pp = i & 15;
        tile[c*17 + pp] = src[(size_t)c*1024 + pp];
    }
    __syncthreads();
    float* dst = g_xt + (size_t)n*262144 + (size_t)s*256;
    unsigned* dq = g_xq + (size_t)n*262144 + (size_t)s*256;
    #pragma unroll
    for (int w = 0; w < 16; w++) {
        float v = tile[t*17 + w];
        dst[(size_t)w*16384 + t] = v;
        dq[(size_t)w*16384 + t] = f2tf(v);
    }
}

// ---------------------------------------------------------------------------
// qkv: [65536 x 256] x [256 x 768] tf32; 512 CTAs x 256 thr (8 warps)
// Each warp: 32 rows x 32 cols (M2 x N4 tiles).
// smem u32: Xs 128 rows stride 260 (33280) + Ws 256 k stride 72 (18432)
// ---------------------------------------------------------------------------
#define QK_WS 33280
#define QK_U32 51712    // 206848 B

__global__ __launch_bounds__(256, 1) void qkv_kernel(
    const float* __restrict__ bq, const float* __restrict__ bk,
    const float* __restrict__ bv) {
    extern __shared__ unsigned sm[];
    unsigned* Xs = sm;
    unsigned* Ws = sm + QK_WS;
    int t = threadIdx.x;
    int w = t >> 5, lane = t & 31;
    int g = lane >> 2, tg = lane & 3;
    int wm = w & 3, wn = w >> 2;      // 4 m-groups x 2 n-groups
    int row0 = blockIdx.x * 128;

    {
        const uint4* xs = (const uint4*)(g_xq + (size_t)row0*256);
        for (int idx = t; idx < 8192; idx += 256) {
            int r = idx >> 6, c4 = idx & 63;
            *(uint4*)(Xs + r*260 + 4*c4) = xs[idx];
        }
    }

    int rbase = wm*32 + g;            // mtile mi -> rows rbase+16*mi (+8)

    for (int nt = 0; nt < 12; nt++) {
        int sel = nt >> 2, nto = nt & 3;
        __syncthreads();
        {
            const unsigned* wsrc = g_wt + sel*65536 + nto*64;
            for (int idx = t; idx < 4096; idx += 256) {
                int k = idx >> 4, c4 = idx & 15;
                *(uint4*)(Ws + k*72 + 4*c4) = *(const uint4*)(wsrc + k*256 + 4*c4);
            }
        }
        __syncthreads();

        float acc[2][4][4];
        #pragma unroll
        for (int mi = 0; mi < 2; mi++)
            #pragma unroll
            for (int nf = 0; nf < 4; nf++)
                #pragma unroll
                for (int j = 0; j < 4; j++) acc[mi][nf][j] = 0.f;

        unsigned aP[2][2][4], bP[2][4][2];
        #pragma unroll
        for (int mi = 0; mi < 2; mi++) {
            int ab = (rbase + 16*mi)*260 + tg;
            aP[0][mi][0] = Xs[ab];     aP[0][mi][1] = Xs[ab + 8*260];
            aP[0][mi][2] = Xs[ab + 4]; aP[0][mi][3] = Xs[ab + 8*260 + 4];
        }
        {
            int w0 = tg*72, w1 = (tg + 4)*72;
            #pragma unroll
            for (int nf = 0; nf < 4; nf++) {
                int col = wn*32 + nf*8 + g;
                bP[0][nf][0] = Ws[w0 + col]; bP[0][nf][1] = Ws[w1 + col];
            }
        }
        #pragma unroll
        for (int s = 0; s < 32; s++) {
            int c = s & 1, nx = c ^ 1;
            if (s < 31) {
                #pragma unroll
                for (int mi = 0; mi < 2; mi++) {
                    int ab = (rbase + 16*mi)*260 + 8*(s+1) + tg;
                    aP[nx][mi][0] = Xs[ab];     aP[nx][mi][1] = Xs[ab + 8*260];
                    aP[nx][mi][2] = Xs[ab + 4]; aP[nx][mi][3] = Xs[ab + 8*260 + 4];
                }
                int w0 = (8*(s+1) + tg)*72, w1 = (8*(s+1) + tg + 4)*72;
                #pragma unroll
                for (int nf = 0; nf < 4; nf++) {
                    int col = wn*32 + nf*8 + g;
                    bP[nx][nf][0] = Ws[w0 + col]; bP[nx][nf][1] = Ws[w1 + col];
                }
            }
            #pragma unroll
            for (int mi = 0; mi < 2; mi++)
                #pragma unroll
                for (int nf = 0; nf < 4; nf++)
                    mma_tf32(acc[mi][nf], aP[c][mi], bP[c][nf][0], bP[c][nf][1]);
        }

        const float* bias = (sel == 0) ? bq : (sel == 1) ? bk : bv;
        unsigned* dst = (sel == 0) ? g_q : (sel == 1) ? g_k : g_vq;
        #pragma unroll
        for (int mi = 0; mi < 2; mi++) {
            size_t rg0 = (size_t)(row0 + rbase + 16*mi), rg1 = rg0 + 8;
            #pragma unroll
            for (int nf = 0; nf < 4; nf++) {
                int mcol = nto*64 + wn*32 + nf*8 + 2*tg;
                float b0 = bias[mcol], b1 = bias[mcol + 1];
                uint2 o0, o1;
                o0.x = f2tf(acc[mi][nf][0] + b0); o0.y = f2tf(acc[mi][nf][1] + b1);
                o1.x = f2tf(acc[mi][nf][2] + b0); o1.y = f2tf(acc[mi][nf][3] + b1);
                *(uint2*)(dst + rg0*256 + mcol) = o0;
                *(uint2*)(dst + rg1*256 + mcol) = o1;
            }
        }
    }
}

// ---------------------------------------------------------------------------
// core: per (batch, head): scores + warp-local softmax + S@V. 128 thr, 4 CTAs/SM
// ---------------------------------------------------------------------------
#define C_Q 0
#define C_K (64*68)
#define C_V (2*64*68)
#define C_U32 (3*64*68)    // 52224 B

__global__ __launch_bounds__(128, 4) void core_kernel() {
    extern __shared__ unsigned sm[];
    int t = threadIdx.x;
    int w = t >> 5, lane = t & 31;
    int g = lane >> 2, tg = lane & 3;
    int b = blockIdx.x, h = blockIdx.y;
    size_t rbase = (size_t)b * 64;

    for (int idx = t; idx < 1024; idx += 128) {
        int s = idx >> 4, c4 = idx & 15;
        *(uint4*)(sm + C_Q + s*68 + 4*c4) = *(const uint4*)(g_q + (rbase + s)*256 + h*64 + 4*c4);
        *(uint4*)(sm + C_K + s*68 + 4*c4) = *(const uint4*)(g_k + (rbase + s)*256 + h*64 + 4*c4);
    }
    for (int idx = t; idx < 4096; idx += 128) {
        int s = idx >> 6, d = idx & 63;
        sm[C_V + d*68 + s] = g_vq[(rbase + s)*256 + h*64 + d];
    }
    __syncthreads();

    int rowA = w*16 + g;

    float sc[8][4];
    #pragma unroll
    for (int i = 0; i < 8; i++) { sc[i][0] = sc[i][1] = sc[i][2] = sc[i][3] = 0.f; }
    #pragma unroll
    for (int s8 = 0; s8 < 8; s8++) {
        unsigned a[4];
        int ab = C_Q + rowA*68 + 8*s8 + tg;
        a[0] = sm[ab]; a[1] = sm[ab + 8*68]; a[2] = sm[ab + 4]; a[3] = sm[ab + 8*68 + 4];
        #pragma unroll
        for (int nf = 0; nf < 8; nf++) {
            int bb = C_K + (nf*8 + g)*68 + 8*s8 + tg;
            mma_tf32(sc[nf], a, sm[bb], sm[bb + 4]);
        }
    }

    const float NI = -3.402823466e38f;
    int rA = rowA, rB = rowA + 8;
    float mA = NI, mB = NI;
    #pragma unroll
    for (int nf = 0; nf < 8; nf++) {
        int c0 = nf*8 + 2*tg, c1 = c0 + 1;
        sc[nf][0] = (c0 <= rA) ? sc[nf][0]*0.125f : NI;
        sc[nf][1] = (c1 <= rA) ? sc[nf][1]*0.125f : NI;
        sc[nf][2] = (c0 <= rB) ? sc[nf][2]*0.125f : NI;
        sc[nf][3] = (c1 <= rB) ? sc[nf][3]*0.125f : NI;
        mA = fmaxf(mA, fmaxf(sc[nf][0], sc[nf][1]));
        mB = fmaxf(mB, fmaxf(sc[nf][2], sc[nf][3]));
    }
    mA = fmaxf(mA, __shfl_xor_sync(0xffffffffu, mA, 1));
    mA = fmaxf(mA, __shfl_xor_sync(0xffffffffu, mA, 2));
    mB = fmaxf(mB, __shfl_xor_sync(0xffffffffu, mB, 1));
    mB = fmaxf(mB, __shfl_xor_sync(0xffffffffu, mB, 2));
    float sA = 0.f, sB = 0.f;
    #pragma unroll
    for (int nf = 0; nf < 8; nf++) {
        int c0 = nf*8 + 2*tg, c1 = c0 + 1;
        float e0 = (c0 <= rA) ? __expf(sc[nf][0] - mA) : 0.f;
        float e1 = (c1 <= rA) ? __expf(sc[nf][1] - mA) : 0.f;
        float e2 = (c0 <= rB) ? __expf(sc[nf][2] - mB) : 0.f;
        float e3 = (c1 <= rB) ? __expf(sc[nf][3] - mB) : 0.f;
        sA += e0 + e1; sB += e2 + e3;
        sc[nf][0] = e0; sc[nf][1] = e1; sc[nf][2] = e2; sc[nf][3] = e3;
    }
    sA += __shfl_xor_sync(0xffffffffu, sA, 1);
    sA += __shfl_xor_sync(0xffffffffu, sA, 2);
    sB += __shfl_xor_sync(0xffffffffu, sB, 1);
    sB += __shfl_xor_sync(0xffffffffu, sB, 2);
    float iA = 1.f / sA, iB = 1.f / sB;
    unsigned P[8][4];
    #pragma unroll
    for (int nf = 0; nf < 8; nf++) {
        P[nf][0] = f2tf(sc[nf][0] * iA);
        P[nf][1] = f2tf(sc[nf][1] * iA);
        P[nf][2] = f2tf(sc[nf][2] * iB);
        P[nf][3] = f2tf(sc[nf][3] * iB);
    }

    float ha[8][4];
    #pragma unroll
    for (int i = 0; i < 8; i++) { ha[i][0] = ha[i][1] = ha[i][2] = ha[i][3] = 0.f; }
    int srcLo = (lane & 28) | (tg >> 1);
    int srcHi = srcLo + 2;
    bool odd = (tg & 1);
    #pragma unroll
    for (int s8 = 0; s8 < 8; s8++) {
        unsigned q00 = __shfl_sync(0xffffffffu, P[s8][0], srcLo);
        unsigned q01 = __shfl_sync(0xffffffffu, P[s8][1], srcLo);
        unsigned q10 = __shfl_sync(0xffffffffu, P[s8][2], srcLo);
        unsigned q11 = __shfl_sync(0xffffffffu, P[s8][3], srcLo);
        unsigned r00 = __shfl_sync(0xffffffffu, P[s8][0], srcHi);
        unsigned r01 = __shfl_sync(0xffffffffu, P[s8][1], srcHi);
        unsigned r10 = __shfl_sync(0xffffffffu, P[s8][2], srcHi);
        unsigned r11 = __shfl_sync(0xffffffffu, P[s8][3], srcHi);
        unsigned a[4];
        a[0] = odd ? q01 : q00;
        a[1] = odd ? q11 : q10;
        a[2] = odd ? r01 : r00;
        a[3] = odd ? r11 : r10;
        #pragma unroll
        for (int nf = 0; nf < 8; nf++) {
            int bb = C_V + (nf*8 + g)*68 + 8*s8 + tg;
            mma_tf32(ha[nf], a, sm[bb], sm[bb + 4]);
        }
    }

    #pragma unroll
    for (int nf = 0; nf < 8; nf++) {
        int gcol = h*64 + nf*8 + 2*tg;
        uint2 o0, o1;
        o0.x = f2tf(ha[nf][0]); o0.y = f2tf(ha[nf][1]);
        o1.x = f2tf(ha[nf][2]); o1.y = f2tf(ha[nf][3]);
        *(uint2*)(g_h + (rbase + rowA)*256 + gcol) = o0;
        *(uint2*)(g_h + (rbase + rowA + 8)*256 + gcol) = o1;
    }
}

// ---------------------------------------------------------------------------
// kout + FUSED scatter-max: [65536 x 256] x Wo + bo + residual, then
// per-batch assignment max -> g_clustered directly (no g_xattn round-trip).
// 512 CTAs x 256 thr; CTA covers 128 rows = 2 batches.
// ---------------------------------------------------------------------------
#define KO_RED QK_U32                 // red: 16*64 floats = 1024 u32
#define KO_IDS (KO_RED + 1024)
#define KO_CNT (KO_IDS + 128)
#define KO_U32 (KO_CNT + 8)           // 52872 u32 = 211488 B

__global__ __launch_bounds__(256, 1) void kout_kernel(const float* __restrict__ bo) {
    extern __shared__ unsigned sm[];
    unsigned* Xs = sm;
    unsigned* Ws = sm + QK_WS;
    float* red = (float*)(sm + KO_RED);
    unsigned* sids = sm + KO_IDS;
    int* cnt = (int*)(sm + KO_CNT);
    int t = threadIdx.x;
    int w = t >> 5, lane = t & 31;
    int g = lane >> 2, tg = lane & 3;
    int wm = w & 3, wn = w >> 2;
    int row0 = blockIdx.x * 128;
    int b0 = blockIdx.x * 2;

    {
        const uint4* xs = (const uint4*)(g_h + (size_t)row0*256);
        for (int idx = t; idx < 8192; idx += 256) {
            int r = idx >> 6, c4 = idx & 63;
            *(uint4*)(Xs + r*260 + 4*c4) = xs[idx];
        }
    }
    if (t < 128) {
        int b = b0 + (t >> 6);
        int p = b & 15, n = b >> 4;
        sids[t] = g_idx[(p*64 + n)*64 + (t & 63)];
    }
    __syncthreads();
    if (t < 8) {
        int batch = t >> 2, k = t & 3, c = 0;
        for (int s = 0; s < 64; s++) c += (sids[batch*64 + s] == (unsigned)k);
        cnt[t] = c;
    }
    __syncthreads();

    int rbase = wm*32 + g;
    unsigned id0 = sids[rbase], id1 = sids[rbase + 8];
    unsigned id2 = sids[rbase + 16], id3 = sids[rbase + 24];
    const float NI = -3.402823466e38f;

    for (int nt = 0; nt < 4; nt++) {
        __syncthreads();
        {
            const unsigned* wsrc = g_wt + 3*65536 + nt*64;
            for (int idx = t; idx < 4096; idx += 256) {
                int k = idx >> 4, c4 = idx & 15;
                *(uint4*)(Ws + k*72 + 4*c4) = *(const uint4*)(wsrc + k*256 + 4*c4);
            }
        }
        __syncthreads();

        float acc[2][4][4];
        #pragma unroll
        for (int mi = 0; mi < 2; mi++)
            #pragma unroll
            for (int nf = 0; nf < 4; nf++)
                #pragma unroll
                for (int j = 0; j < 4; j++) acc[mi][nf][j] = 0.f;

        unsigned aP[2][2][4], bP[2][4][2];
        #pragma unroll
        for (int mi = 0; mi < 2; mi++) {
            int ab = (rbase + 16*mi)*260 + tg;
            aP[0][mi][0] = Xs[ab];     aP[0][mi][1] = Xs[ab + 8*260];
            aP[0][mi][2] = Xs[ab + 4]; aP[0][mi][3] = Xs[ab + 8*260 + 4];
        }
        {
            int w0 = tg*72, w1 = (tg + 4)*72;
            #pragma unroll
            for (int nf = 0; nf < 4; nf++) {
                int col = wn*32 + nf*8 + g;
                bP[0][nf][0] = Ws[w0 + col]; bP[0][nf][1] = Ws[w1 + col];
            }
        }
        #pragma unroll
        for (int s = 0; s < 32; s++) {
            int c = s & 1, nx = c ^ 1;
            if (s < 31) {
                #pragma unroll
                for (int mi = 0; mi < 2; mi++) {
                    int ab = (rbase + 16*mi)*260 + 8*(s+1) + tg;
                    aP[nx][mi][0] = Xs[ab];     aP[nx][mi][1] = Xs[ab + 8*260];
                    aP[nx][mi][2] = Xs[ab + 4]; aP[nx][mi][3] = Xs[ab + 8*260 + 4];
                }
                int w0 = (8*(s+1) + tg)*72, w1 = (8*(s+1) + tg + 4)*72;
                #pragma unroll
                for (int nf = 0; nf < 4; nf++) {
                    int col = wn*32 + nf*8 + g;
                    bP[nx][nf][0] = Ws[w0 + col]; bP[nx][nf][1] = Ws[w1 + col];
                }
            }
            #pragma unroll
            for (int mi = 0; mi < 2; mi++)
                #pragma unroll
                for (int nf = 0; nf < 4; nf++)
                    mma_tf32(acc[mi][nf], aP[c][mi], bP[c][nf][0], bP[c][nf][1]);
        }

        // fused epilogue: residual + per-k max over this thread's 4 rows,
        // reduce over g via shfl, stage per-warp result in smem.
        #pragma unroll
        for (int nf = 0; nf < 4; nf++) {
            int mcol = nt*64 + wn*32 + nf*8 + 2*tg;
            float bz0 = bo[mcol], bz1 = bo[mcol + 1];
            size_t r0g = (size_t)(row0 + rbase);
            float2 x0 = *(const float2*)(g_xt + r0g*256 + mcol);
            float2 x1 = *(const float2*)(g_xt + (r0g + 8)*256 + mcol);
            float2 x2 = *(const float2*)(g_xt + (r0g + 16)*256 + mcol);
            float2 x3 = *(const float2*)(g_xt + (r0g + 24)*256 + mcol);
            float o00 = acc[0][nf][0] + bz0 + x0.x, o01 = acc[0][nf][1] + bz1 + x0.y;
            float o10 = acc[0][nf][2] + bz0 + x1.x, o11 = acc[0][nf][3] + bz1 + x1.y;
            float o20 = acc[1][nf][0] + bz0 + x2.x, o21 = acc[1][nf][1] + bz1 + x2.y;
            float o30 = acc[1][nf][2] + bz0 + x3.x, o31 = acc[1][nf][3] + bz1 + x3.y;
            #pragma unroll
            for (int k = 0; k < 4; k++) {
                float p0 = fmaxf(fmaxf(id0 == (unsigned)k ? o00 : NI,
                                       id1 == (unsigned)k ? o10 : NI),
                                 fmaxf(id2 == (unsigned)k ? o20 : NI,
                                       id3 == (unsigned)k ? o30 : NI));
                float p1 = fmaxf(fmaxf(id0 == (unsigned)k ? o01 : NI,
                                       id1 == (unsigned)k ? o11 : NI),
                                 fmaxf(id2 == (unsigned)k ? o21 : NI,
                                       id3 == (unsigned)k ? o31 : NI));
                p0 = fmaxf(p0, __shfl_xor_sync(0xffffffffu, p0, 4));
                p0 = fmaxf(p0, __shfl_xor_sync(0xffffffffu, p0, 8));
                p0 = fmaxf(p0, __shfl_xor_sync(0xffffffffu, p0, 16));
                p1 = fmaxf(p1, __shfl_xor_sync(0xffffffffu, p1, 4));
                p1 = fmaxf(p1, __shfl_xor_sync(0xffffffffu, p1, 8));
                p1 = fmaxf(p1, __shfl_xor_sync(0xffffffffu, p1, 16));
                if (lane < 4) {
                    int lc = wn*32 + nf*8 + 2*tg;
                    red[(wm*4 + k)*64 + lc]     = p0;
                    red[(wm*4 + k)*64 + lc + 1] = p1;
                }
            }
        }
        __syncthreads();
        // combine the two wm-warps of each batch, apply zero rule, write out
        for (int e = t; e < 512; e += 256) {
            int batch = e >> 8, k = (e >> 6) & 3, lc = e & 63;
            float m = fmaxf(red[((batch*2)*4 + k)*64 + lc],
                            red[((batch*2 + 1)*4 + k)*64 + lc]);
            if (cnt[batch*4 + k] < 64) m = fmaxf(m, 0.f);
            int b = b0 + batch;
            int p = b & 15, n = b >> 4;
            g_clustered[(size_t)((p*64 + n)*1024 + k*256 + nt*64 + lc)] = m;
        }
    }
}

// ---------------------------------------------------------------------------
// Kernel 1: normalize prototypes
// ---------------------------------------------------------------------------
__global__ void protonorm_kernel(const float* __restrict__ prot) {
    int r = blockIdx.x;
    int t = threadIdx.x;
    float v = prot[r*256 + t];
    float sq = v * v;
    #pragma unroll
    for (int off = 16; off > 0; off >>= 1)
        sq += __shfl_down_sync(0xffffffffu, sq, off);
    __shared__ float red[8];
    if ((t & 31) == 0) red[t >> 5] = sq;
    __syncthreads();
    __shared__ float rn;
    if (t == 0) {
        float sum = 0.f;
        #pragma unroll
        for (int i = 0; i < 8; i++) sum += red[i];
        rn = rsqrtf(sum);
    }
    __syncthreads();
    g_protn[r*256 + t] = v * rn;
}

// ---------------------------------------------------------------------------
// Kernel 2: instance-norm + dot + argmax -> hard idx
// ---------------------------------------------------------------------------
__global__ __launch_bounds__(256) void assign_kernel() {
    int p = blockIdx.x, n = blockIdx.y;
    extern __shared__ float smf[];
    float* Xs = smf;
    float* P  = Xs + 16384;
    float* MU = P + 1024;
    float* RS = MU + 256;
    int t = threadIdx.x;
    const float* src = g_xt + (size_t)(n*16 + p) * 16384;
    for (int i = t; i < 16384; i += 256) Xs[i] = src[i];
    const float* psrc = g_protn + p*1024;
    for (int i = t; i < 1024; i += 256) P[i] = psrc[i];
    __syncthreads();

    {
        float s1 = 0.f, s2 = 0.f;
        #pragma unroll
        for (int s = 0; s < 64; s++) {
            float v = Xs[s*256 + t];
            s1 += v; s2 += v*v;
        }
        float mu = s1 * 0.015625f;
        float var = s2 * 0.015625f - mu*mu;
        MU[t] = mu;
        RS[t] = rsqrtf(var + 1e-5f);
    }
    __syncthreads();

    int w = t >> 5, lane = t & 31;
    #pragma unroll
    for (int it = 0; it < 8; it++) {
        int s = w*8 + it;
        float d0 = 0.f, d1 = 0.f, d2 = 0.f, d3 = 0.f;
        #pragma unroll
        for (int cc = 0; cc < 8; cc++) {
            int c = lane + 32*cc;
            float y = (Xs[s*256 + c] - MU[c]) * RS[c];
            d0 = fmaf(y, P[c],       d0);
            d1 = fmaf(y, P[256 + c], d1);
            d2 = fmaf(y, P[512 + c], d2);
            d3 = fmaf(y, P[768 + c], d3);
        }
        #pragma unroll
        for (int off = 16; off > 0; off >>= 1) {
            d0 += __shfl_down_sync(0xffffffffu, d0, off);
            d1 += __shfl_down_sync(0xffffffffu, d1, off);
            d2 += __shfl_down_sync(0xffffffffu, d2, off);
            d3 += __shfl_down_sync(0xffffffffu, d3, off);
        }
        if (lane == 0) {
            int best = 0; float bv = d0;
            if (d1 > bv) { bv = d1; best = 1; }
            if (d2 > bv) { bv = d2; best = 2; }
            if (d3 > bv) { bv = d3; best = 3; }
            g_idx[(p*64 + n)*64 + s] = (unsigned char)best;
        }
    }
}

// ---------------------------------------------------------------------------
// Kernel 3: mode over parts -> cluster_indices (as float)
// ---------------------------------------------------------------------------
__global__ void mode_kernel(float* __restrict__ outci) {
    int id = blockIdx.x*256 + threadIdx.x;
    if (id >= NN*SS) return;
    int n = id >> 6, s = id & 63;
    int c0 = 0, c1 = 0, c2 = 0, c3 = 0;
    #pragma unroll
    for (int p = 0; p < 16; p++) {
        int a = g_idx[(p*64 + n)*64 + s];
        c0 += (a == 0); c1 += (a == 1); c2 += (a == 2); c3 += (a == 3);
    }
    int best = 0, bc = c0;
    if (c1 > bc) { bc = c1; best = 1; }
    if (c2 > bc) { bc = c2; best = 2; }
    if (c3 > bc) { bc = c3; best = 3; }
    outci[id] = (float)best;
}

// ---------------------------------------------------------------------------
// Kernel 6: per-part FC
// ---------------------------------------------------------------------------
__global__ __launch_bounds__(256) void fc_kernel(const float* __restrict__ fcb,
                                                 float* __restrict__ out) {
    int p = blockIdx.x, n0 = blockIdx.y * 16, t = threadIdx.x;
    extern __shared__ float cl[];
    for (int nn = 0; nn < 16; nn++) {
        const float* src = g_clustered + (size_t)(p*64 + n0 + nn)*1024;
        for (int i = t; i < 1024; i += 256) cl[nn*1024 + i] = src[i];
    }
    __syncthreads();
    int o0 = t & 63, g = t >> 6;
    float acc[4][4];
    #pragma unroll
    for (int a = 0; a < 4; a++)
        #pragma unroll
        for (int bb = 0; bb < 4; bb++) acc[a][bb] = 0.f;
    const float* F = fcb + (size_t)p*1024*256 + o0;
    for (int kc = 0; kc < 1024; kc++) {
        float wv[4], cv[4];
        #pragma unroll
        for (int bb = 0; bb < 4; bb++) wv[bb] = F[(size_t)kc*256 + 64*bb];
        #pragma unroll
        for (int a = 0; a < 4; a++) cv[a] = cl[(g*4 + a)*1024 + kc];
        #pragma unroll
        for (int a = 0; a < 4; a++)
            #pragma unroll
            for (int bb = 0; bb < 4; bb++)
                acc[a][bb] = fmaf(cv[a], wv[bb], acc[a][bb]);
    }
    #pragma unroll
    for (int a = 0; a < 4; a++) {
        int n = n0 + g*4 + a;
        #pragma unroll
        for (int bb = 0; bb < 4; bb++) {
            int o = o0 + 64*bb;
            out[(size_t)n*4096 + o*16 + p] = acc[a][bb];
        }
    }
}

// ---------------------------------------------------------------------------
extern "C" void kernel_launch(void* const* d_in, const int* in_sizes, int n_in,
                              void* d_out, int out_size) {
    const float* x    = (const float*)d_in[0];
    const float* prot = (const float*)d_in[1];
    const float* Wq   = (const float*)d_in[2];
    const float* bq   = (const float*)d_in[3];
    const float* Wk   = (const float*)d_in[4];
    const float* bk   = (const float*)d_in[5];
    const float* Wv   = (const float*)d_in[6];
    const float* bv   = (const float*)d_in[7];
    const float* Wo   = (const float*)d_in[8];
    const float* bo   = (const float*)d_in[9];
    const float* fcb  = (const float*)d_in[10];
    float* out = (float*)d_out;

    cudaFuncSetAttribute(qkv_kernel,  cudaFuncAttributeMaxDynamicSharedMemorySize, QK_U32*4);
    cudaFuncSetAttribute(kout_kernel, cudaFuncAttributeMaxDynamicSharedMemorySize, KO_U32*4);
    cudaFuncSetAttribute(core_kernel, cudaFuncAttributeMaxDynamicSharedMemorySize, C_U32*4);
    cudaFuncSetAttribute(assign_kernel, cudaFuncAttributeMaxDynamicSharedMemorySize, 71680);
    cudaFuncSetAttribute(fc_kernel, cudaFuncAttributeMaxDynamicSharedMemorySize, 65536);

    transpose_kernel<<<NN*SS, 256>>>(x);
    packw_kernel<<<dim3(256, 4), 256>>>(Wq, Wk, Wv, Wo);
    protonorm_kernel<<<PP*KK, 256>>>(prot);
    assign_kernel<<<dim3(PP, NN), 256, 71680>>>();
    qkv_kernel<<<512, 256, QK_U32*4>>>(bq, bk, bv);
    core_kernel<<<dim3(NB, 4), 128, C_U32*4>>>();
    kout_kernel<<<512, 256, KO_U32*4>>>(bo);
    if (out_size >= NN*CC*PP + NN*SS)
        mode_kernel<<<16, 256>>>(out + NN*CC*PP);
    fc_kernel<<<dim3(PP, 4), 256, 65536>>>(fcb, out);
}